// round 15
// baseline (speedup 1.0000x reference)
#include <cuda_runtime.h>
#include <cuda_bf16.h>
#include <math.h>
#include <stdint.h>

#define Bb 8
#define Tt 8192
#define Ss 8192
#define Ff 64
#define Dd 64
#define EPSf 1e-9f
#define KVPAD 72
#define NCHUNK 1024   /* global 64-row chunks: 8 batches x 128 */

// kv scratch [b][256][72]; col 64 = normalizer, 65..71 stay zero
__device__ __align__(16) float g_kv[Bb * 256 * KVPAD];
__device__ unsigned g_bar = 0;   // monotonic grid-barrier counter (replay-safe)

// ---------------------------------------------------------------------------
// helpers
// ---------------------------------------------------------------------------
__device__ __forceinline__ float ftf32(float x) {
    unsigned u;
    asm("cvt.rna.tf32.f32 %0, %1;" : "=r"(u) : "f"(x));
    return __uint_as_float(u);
}

__device__ __forceinline__ uint32_t packbf(float x0, float x1) {
    uint32_t u;
    asm("cvt.rn.bf16x2.f32 %0, %1, %2;" : "=r"(u) : "f"(x1), "f"(x0));
    return u;
}

__device__ __forceinline__ void split2(float x0, float x1,
                                       uint32_t& hw, uint32_t& lw) {
    float h0 = __bfloat162float(__float2bfloat16(x0));
    float h1 = __bfloat162float(__float2bfloat16(x1));
    hw = packbf(x0, x1);
    lw = packbf(x0 - h0, x1 - h1);
}

// tf32 m16n8k8 (GEMM3/GEMM4)
__device__ __forceinline__ void mma8(float4& d,
                                     float a0, float a1, float a2, float a3,
                                     float b0, float b1) {
    asm("mma.sync.aligned.m16n8k8.row.col.f32.tf32.tf32.f32 "
        "{%0,%1,%2,%3},{%4,%5,%6,%7},{%8,%9},{%0,%1,%2,%3};"
        : "+f"(d.x), "+f"(d.y), "+f"(d.z), "+f"(d.w)
        : "r"(__float_as_uint(a0)), "r"(__float_as_uint(a1)),
          "r"(__float_as_uint(a2)), "r"(__float_as_uint(a3)),
          "r"(__float_as_uint(b0)), "r"(__float_as_uint(b1)));
}

// bf16 m16n8k16 (GEMM1)
__device__ __forceinline__ void mma16(float4& d,
                                      uint32_t a0, uint32_t a1,
                                      uint32_t a2, uint32_t a3,
                                      uint32_t b0, uint32_t b1) {
    asm("mma.sync.aligned.m16n8k16.row.col.f32.bf16.bf16.f32 "
        "{%0,%1,%2,%3},{%4,%5,%6,%7},{%8,%9},{%0,%1,%2,%3};"
        : "+f"(d.x), "+f"(d.y), "+f"(d.z), "+f"(d.w)
        : "r"(a0), "r"(a1), "r"(a2), "r"(a3), "r"(b0), "r"(b1));
}

// L2-direct vector load (bypass L1 — g_kv was updated via L2 atomics)
__device__ __forceinline__ float4 ldcg4(const float4* p) {
    float4 v;
    asm volatile("ld.global.cg.v4.f32 {%0, %1, %2, %3}, [%4];"
                 : "=f"(v.x), "=f"(v.y), "=f"(v.z), "=f"(v.w) : "l"(p));
    return v;
}

// grid barrier: all blocks co-resident (grid == #SMs, 1 block/SM via smem)
__device__ __forceinline__ void grid_barrier() {
    __syncthreads();
    if (threadIdx.x == 0) {
        __threadfence();
        unsigned old = atomicAdd(&g_bar, 1u);
        unsigned target = old - (old % gridDim.x) + gridDim.x;
        while (atomicAdd(&g_bar, 0u) < target) {}
        __threadfence();
    }
    __syncthreads();
}

// ---------------------------------------------------------------------------
// smem layouts (32-bit word offsets) — A and B phases overlap (union)
// ---------------------------------------------------------------------------
// phase A
#define A_KHI   0        /* [64][36]  packed bf16x2 hi */
#define A_KLO   2304     /* [64][36]  packed bf16x2 lo */
#define A_VS    4608     /* [64][72]  tf32 floats      */
#define A_PHT   9216     /* [256][68] tf32 floats      */
#define A_OHIP  26624    /* [128][36] packed hi        */
#define A_OLOP  31232    /* [128][36] packed lo        */
#define A_SSH   35840    /* [64]  */
#define A_TOT   35904
// phase B
#define B_QHI   0        /* [64][36]   */
#define B_QLO   2304     /* [64][36]   */
#define B_OHP   4608     /* [128][36]  */
#define B_OLP   9216     /* [128][36]  */
#define B_PHIQ  13824    /* [64][260]  */
#define B_KVS   30464    /* [256][72]  */
#define B_SSH   48896    /* [64]       */
#define B_TOT   48960

extern __shared__ float sm[];

// ---------------------------------------------------------------------------
// Fused persistent kernel: zero -> barrier -> A (kv) -> barrier -> B (out)
// ---------------------------------------------------------------------------
__global__ __launch_bounds__(256, 1)
void fused_kernel(const float* __restrict__ query,
                  const float* __restrict__ value,
                  const float* __restrict__ key,
                  const float* __restrict__ omega,
                  float* __restrict__ outp) {
    const int tid = threadIdx.x;
    const int w   = tid >> 5;
    const int ln  = tid & 31;
    const int gid = ln >> 2;
    const int tq  = ln & 3;
    const int r   = tid >> 2;
    const int qd  = tid & 3;

    const int lo = (int)(((long long)NCHUNK * blockIdx.x) / gridDim.x);
    const int hi = (int)(((long long)NCHUNK * (blockIdx.x + 1)) / gridDim.x);

    // ======================= phase 0: zero g_kv ============================
    {
        float4 zz = make_float4(0.f, 0.f, 0.f, 0.f);
        for (int i = blockIdx.x * 256 + tid; i < Bb * 256 * KVPAD / 4;
             i += gridDim.x * 256)
            ((float4*)g_kv)[i] = zz;
    }
    grid_barrier();

    // ======================= phase A: kv accumulation ======================
    {
        uint32_t* Khi = (uint32_t*)(sm + A_KHI);
        uint32_t* Klo = (uint32_t*)(sm + A_KLO);
        float*    Vs  = sm + A_VS;
        float*    PhT = sm + A_PHT;
        uint32_t* Ohp = (uint32_t*)(sm + A_OHIP);
        uint32_t* Olp = (uint32_t*)(sm + A_OLOP);
        float*    ssh = sm + A_SSH;

        // omega -> packed bf16 hi/lo split in smem (once per block)
        for (int i = tid; i < 128 * 32; i += 256) {
            int m = i >> 5, wj = i & 31;
            uint32_t hw, lw;
            split2(omega[m * 64 + 2 * wj], omega[m * 64 + 2 * wj + 1], hw, lw);
            Ohp[m * 36 + wj] = hw;
            Olp[m * 36 + wj] = lw;
        }

        float4 acc[2][8];
        #pragma unroll
        for (int mt = 0; mt < 2; mt++)
            #pragma unroll
            for (int nt = 0; nt < 8; nt++)
                acc[mt][nt] = make_float4(0.f, 0.f, 0.f, 0.f);
        float nrm[2][2] = {{0.f, 0.f}, {0.f, 0.f}};

        // preload chunk lo
        float4 kreg[4], vreg[4];
        if (lo < hi) {
            const float4* kg = (const float4*)(key   + ((size_t)lo * 64 + r) * Ff);
            const float4* vg = (const float4*)(value + ((size_t)lo * 64 + r) * Dd);
            #pragma unroll
            for (int j = 0; j < 4; j++) { kreg[j] = kg[qd * 4 + j]; vreg[j] = vg[qd * 4 + j]; }
        }

        for (int g = lo; g < hi; g++) {
            __syncthreads();   // previous-iter PhT/Vs/tile/ssh reads done

            // ---- store staged K (split bf16) / V (tf32); ssq via quad shfl ----
            {
                float ps = 0.f;
                #pragma unroll
                for (int j = 0; j < 4; j++) {
                    int fj = qd * 4 + j;
                    float4 x = kreg[j];
                    ps += x.x * x.x + x.y * x.y + x.z * x.z + x.w * x.w;
                    uint32_t hw, lw;
                    split2(x.x, x.y, hw, lw);
                    Khi[r * 36 + 2 * fj] = hw;  Klo[r * 36 + 2 * fj] = lw;
                    split2(x.z, x.w, hw, lw);
                    Khi[r * 36 + 2 * fj + 1] = hw;  Klo[r * 36 + 2 * fj + 1] = lw;
                }
                ps += __shfl_xor_sync(0xffffffffu, ps, 1);
                ps += __shfl_xor_sync(0xffffffffu, ps, 2);
                if (qd == 0) ssh[r] = 0.5f * ps;
                #pragma unroll
                for (int j = 0; j < 4; j++) {
                    float4 x = vreg[j];
                    float4 y;
                    y.x = ftf32(x.x); y.y = ftf32(x.y); y.z = ftf32(x.z); y.w = ftf32(x.w);
                    ((float4*)(Vs + r * 72))[qd * 4 + j] = y;
                }
                if (g + 1 < hi) {   // prefetch next chunk
                    const float4* kg = (const float4*)(key   + ((size_t)(g + 1) * 64 + r) * Ff);
                    const float4* vg = (const float4*)(value + ((size_t)(g + 1) * 64 + r) * Dd);
                    #pragma unroll
                    for (int j = 0; j < 4; j++) { kreg[j] = kg[qd * 4 + j]; vreg[j] = vg[qd * 4 + j]; }
                }
            }
            __syncthreads();

            // ---- XW = K . Omega^T (split-bf16 k16; warp w: feats [16w,16w+16)) ----
            float4 xw[4][2];
            #pragma unroll
            for (int mt = 0; mt < 4; mt++)
                #pragma unroll
                for (int nt = 0; nt < 2; nt++)
                    xw[mt][nt] = make_float4(0.f, 0.f, 0.f, 0.f);

            #pragma unroll
            for (int ks = 0; ks < 4; ks++) {
                int f0w = ks * 8 + tq;
                uint32_t bh[2][2], bl[2][2];
                #pragma unroll
                for (int nt = 0; nt < 2; nt++) {
                    int m = w * 16 + nt * 8 + gid;
                    bh[nt][0] = Ohp[m * 36 + f0w];  bh[nt][1] = Ohp[m * 36 + f0w + 4];
                    bl[nt][0] = Olp[m * 36 + f0w];  bl[nt][1] = Olp[m * 36 + f0w + 4];
                }
                #pragma unroll
                for (int mt = 0; mt < 4; mt++) {
                    int s = mt * 16 + gid;
                    uint32_t ah0 = Khi[s * 36 + f0w],       ah1 = Khi[(s + 8) * 36 + f0w];
                    uint32_t ah2 = Khi[s * 36 + f0w + 4],   ah3 = Khi[(s + 8) * 36 + f0w + 4];
                    uint32_t al0 = Klo[s * 36 + f0w],       al1 = Klo[(s + 8) * 36 + f0w];
                    uint32_t al2 = Klo[s * 36 + f0w + 4],   al3 = Klo[(s + 8) * 36 + f0w + 4];
                    #pragma unroll
                    for (int nt = 0; nt < 2; nt++) {
                        mma16(xw[mt][nt], ah0, ah1, ah2, ah3, bh[nt][0], bh[nt][1]);
                        mma16(xw[mt][nt], al0, al1, al2, al3, bh[nt][0], bh[nt][1]);
                        mma16(xw[mt][nt], ah0, ah1, ah2, ah3, bl[nt][0], bl[nt][1]);
                    }
                }
            }

            // ---- phi epilogue: PhT[m][s] = tf32(exp(+-xw - ss) + eps) ----
            #pragma unroll
            for (int mt = 0; mt < 4; mt++) {
                int s0 = mt * 16 + gid;
                float ssa = ssh[s0], ssb = ssh[s0 + 8];
                #pragma unroll
                for (int nt = 0; nt < 2; nt++) {
                    int m0 = w * 16 + nt * 8 + 2 * tq;
                    float4 v = xw[mt][nt];
                    PhT[m0 * 68 + s0]             = ftf32(__expf( v.x - ssa) + EPSf);
                    PhT[(m0 + 1) * 68 + s0]       = ftf32(__expf( v.y - ssa) + EPSf);
                    PhT[m0 * 68 + s0 + 8]         = ftf32(__expf( v.z - ssb) + EPSf);
                    PhT[(m0 + 1) * 68 + s0 + 8]   = ftf32(__expf( v.w - ssb) + EPSf);
                    PhT[(m0 + 128) * 68 + s0]     = ftf32(__expf(-v.x - ssa) + EPSf);
                    PhT[(m0 + 129) * 68 + s0]     = ftf32(__expf(-v.y - ssa) + EPSf);
                    PhT[(m0 + 128) * 68 + s0 + 8] = ftf32(__expf(-v.z - ssb) + EPSf);
                    PhT[(m0 + 129) * 68 + s0 + 8] = ftf32(__expf(-v.w - ssb) + EPSf);
                }
            }
            __syncthreads();

            // ---- acc += PhT . V (tf32 k8; warp w owns kv rows [32w,32w+32)) ----
            #pragma unroll 2
            for (int ks = 0; ks < 8; ks++) {
                float a[2][4];
                #pragma unroll
                for (int mt = 0; mt < 2; mt++) {
                    int mr = 32 * w + mt * 16 + gid;
                    int sc = ks * 8 + tq;
                    a[mt][0] = PhT[mr * 68 + sc];
                    a[mt][1] = PhT[(mr + 8) * 68 + sc];
                    a[mt][2] = PhT[mr * 68 + sc + 4];
                    a[mt][3] = PhT[(mr + 8) * 68 + sc + 4];
                    nrm[mt][0] += a[mt][0] + a[mt][2];
                    nrm[mt][1] += a[mt][1] + a[mt][3];
                }
                #pragma unroll
                for (int nt = 0; nt < 8; nt++) {
                    float b0 = Vs[(ks * 8 + tq) * 72 + nt * 8 + gid];
                    float b1 = Vs[(ks * 8 + tq + 4) * 72 + nt * 8 + gid];
                    #pragma unroll
                    for (int mt = 0; mt < 2; mt++)
                        mma8(acc[mt][nt], a[mt][0], a[mt][1], a[mt][2], a[mt][3], b0, b1);
                }
            }

            // ---- flush on batch change or range end ----
            if (g + 1 == hi || ((g + 1) >> 7) != (g >> 7)) {
                float* gp = g_kv + (size_t)(g >> 7) * 256 * KVPAD;
                #pragma unroll
                for (int mt = 0; mt < 2; mt++) {
                    int m0 = 32 * w + mt * 16 + gid;
                    #pragma unroll
                    for (int nt = 0; nt < 8; nt++) {
                        int d0 = nt * 8 + 2 * tq;
                        atomicAdd(gp + m0 * KVPAD + d0,           acc[mt][nt].x);
                        atomicAdd(gp + m0 * KVPAD + d0 + 1,       acc[mt][nt].y);
                        atomicAdd(gp + (m0 + 8) * KVPAD + d0,     acc[mt][nt].z);
                        atomicAdd(gp + (m0 + 8) * KVPAD + d0 + 1, acc[mt][nt].w);
                        acc[mt][nt] = make_float4(0.f, 0.f, 0.f, 0.f);
                    }
                    float n0 = nrm[mt][0], n1 = nrm[mt][1];
                    n0 += __shfl_xor_sync(0xffffffffu, n0, 1);
                    n0 += __shfl_xor_sync(0xffffffffu, n0, 2);
                    n1 += __shfl_xor_sync(0xffffffffu, n1, 1);
                    n1 += __shfl_xor_sync(0xffffffffu, n1, 2);
                    if (tq == 0) {
                        atomicAdd(gp + m0 * KVPAD + 64,       n0);
                        atomicAdd(gp + (m0 + 8) * KVPAD + 64, n1);
                    }
                    nrm[mt][0] = 0.f; nrm[mt][1] = 0.f;
                }
            }
        }
    }
    grid_barrier();

    // ======================= phase B: output ===============================
    {
        uint32_t* Qhi  = (uint32_t*)(sm + B_QHI);
        uint32_t* Qlo  = (uint32_t*)(sm + B_QLO);
        uint32_t* Ohp  = (uint32_t*)(sm + B_OHP);
        uint32_t* Olp  = (uint32_t*)(sm + B_OLP);
        float*    PhiQ = sm + B_PHIQ;
        float*    kvs  = sm + B_KVS;
        float*    ssh  = sm + B_SSH;

        // omega split (once per block)
        for (int i = tid; i < 128 * 32; i += 256) {
            int m = i >> 5, wj = i & 31;
            uint32_t hw, lw;
            split2(omega[m * 64 + 2 * wj], omega[m * 64 + 2 * wj + 1], hw, lw);
            Ohp[m * 36 + wj] = hw;
            Olp[m * 36 + wj] = lw;
        }
        __syncthreads();   // omega split vs phase-A smem reuse

        int bcur = -1;

        for (int u = lo; u < hi; u++) {
            __syncthreads();   // prev tile's PhiQ/kvs/Q/ssh reads done
            const int b = u >> 7;

            if (b != bcur) {   // (re)load kv, tf32-rounded, L2-direct
                const float4* gk = (const float4*)(g_kv + (size_t)b * 256 * KVPAD);
                for (int i = tid; i < 256 * KVPAD / 4; i += 256) {
                    float4 x = ldcg4(gk + i);
                    float4 y;
                    y.x = ftf32(x.x); y.y = ftf32(x.y); y.z = ftf32(x.z); y.w = ftf32(x.w);
                    ((float4*)kvs)[i] = y;
                }
                bcur = b;
            }

            // Q tile (64 rows): split bf16 + ssq via quad shfl
            {
                const float4* qg = (const float4*)(query + ((size_t)u * 64 + r) * Ff);
                float ps = 0.f;
                #pragma unroll
                for (int j = 0; j < 4; j++) {
                    int fj = qd * 4 + j;
                    float4 x = qg[fj];
                    ps += x.x * x.x + x.y * x.y + x.z * x.z + x.w * x.w;
                    uint32_t hw, lw;
                    split2(x.x, x.y, hw, lw);
                    Qhi[r * 36 + 2 * fj] = hw;  Qlo[r * 36 + 2 * fj] = lw;
                    split2(x.z, x.w, hw, lw);
                    Qhi[r * 36 + 2 * fj + 1] = hw;  Qlo[r * 36 + 2 * fj + 1] = lw;
                }
                ps += __shfl_xor_sync(0xffffffffu, ps, 1);
                ps += __shfl_xor_sync(0xffffffffu, ps, 2);
                if (qd == 0) ssh[r] = 0.5f * ps;
            }
            __syncthreads();

            // ---- XW = Q . Omega^T (split-bf16 k16; warp w: feats [16w,16w+16)) ----
            float4 xw[4][2];
            #pragma unroll
            for (int mt = 0; mt < 4; mt++)
                #pragma unroll
                for (int nt = 0; nt < 2; nt++)
                    xw[mt][nt] = make_float4(0.f, 0.f, 0.f, 0.f);

            #pragma unroll
            for (int ks = 0; ks < 4; ks++) {
                int f0w = ks * 8 + tq;
                uint32_t bh[2][2], bl[2][2];
                #pragma unroll
                for (int nt = 0; nt < 2; nt++) {
                    int m = w * 16 + nt * 8 + gid;
                    bh[nt][0] = Ohp[m * 36 + f0w];  bh[nt][1] = Ohp[m * 36 + f0w + 4];
                    bl[nt][0] = Olp[m * 36 + f0w];  bl[nt][1] = Olp[m * 36 + f0w + 4];
                }
                #pragma unroll
                for (int mt = 0; mt < 4; mt++) {
                    int t = mt * 16 + gid;
                    uint32_t ah0 = Qhi[t * 36 + f0w],       ah1 = Qhi[(t + 8) * 36 + f0w];
                    uint32_t ah2 = Qhi[t * 36 + f0w + 4],   ah3 = Qhi[(t + 8) * 36 + f0w + 4];
                    uint32_t al0 = Qlo[t * 36 + f0w],       al1 = Qlo[(t + 8) * 36 + f0w];
                    uint32_t al2 = Qlo[t * 36 + f0w + 4],   al3 = Qlo[(t + 8) * 36 + f0w + 4];
                    #pragma unroll
                    for (int nt = 0; nt < 2; nt++) {
                        mma16(xw[mt][nt], ah0, ah1, ah2, ah3, bh[nt][0], bh[nt][1]);
                        mma16(xw[mt][nt], al0, al1, al2, al3, bh[nt][0], bh[nt][1]);
                        mma16(xw[mt][nt], ah0, ah1, ah2, ah3, bl[nt][0], bl[nt][1]);
                    }
                }
            }

            // ---- phi epilogue: PhiQ[t][m] = tf32(exp(+-xw - ss) + eps) ----
            #pragma unroll
            for (int mt = 0; mt < 4; mt++) {
                int t = mt * 16 + gid;
                float ssa = ssh[t], ssb = ssh[t + 8];
                #pragma unroll
                for (int nt = 0; nt < 2; nt++) {
                    int m0 = w * 16 + nt * 8 + 2 * tq;
                    float4 v = xw[mt][nt];
                    PhiQ[t * 260 + m0]             = ftf32(__expf( v.x - ssa) + EPSf);
                    PhiQ[t * 260 + m0 + 1]         = ftf32(__expf( v.y - ssa) + EPSf);
                    PhiQ[(t + 8) * 260 + m0]       = ftf32(__expf( v.z - ssb) + EPSf);
                    PhiQ[(t + 8) * 260 + m0 + 1]   = ftf32(__expf( v.w - ssb) + EPSf);
                    PhiQ[t * 260 + m0 + 128]       = ftf32(__expf(-v.x - ssa) + EPSf);
                    PhiQ[t * 260 + m0 + 129]       = ftf32(__expf(-v.y - ssa) + EPSf);
                    PhiQ[(t + 8) * 260 + m0 + 128] = ftf32(__expf(-v.z - ssb) + EPSf);
                    PhiQ[(t + 8) * 260 + m0 + 129] = ftf32(__expf(-v.w - ssb) + EPSf);
                }
            }
            __syncthreads();

            // ---- out = PhiQ . kv (tf32 k8; warp-halves over 8 n-tiles) ----
            const int half = w >> 2;
            const int wr   = w & 3;
            const int tr   = 16 * wr + gid;

            float4 oacc[4];
            #pragma unroll
            for (int nt = 0; nt < 4; nt++) oacc[nt] = make_float4(0.f, 0.f, 0.f, 0.f);
            float nrm0 = 0.f, nrm1 = 0.f;

            #pragma unroll 4
            for (int ks = 0; ks < 32; ks++) {
                int mc = ks * 8 + tq;
                float a0 = PhiQ[tr * 260 + mc],       a1 = PhiQ[(tr + 8) * 260 + mc];
                float a2 = PhiQ[tr * 260 + mc + 4],   a3 = PhiQ[(tr + 8) * 260 + mc + 4];
                float kn0 = kvs[mc * KVPAD + 64];
                float kn1 = kvs[(mc + 4) * KVPAD + 64];
                nrm0 += a0 * kn0 + a2 * kn1;
                nrm1 += a1 * kn0 + a3 * kn1;
                #pragma unroll
                for (int nt = 0; nt < 4; nt++) {
                    int ntg = half * 4 + nt;
                    float b0 = kvs[mc * KVPAD + ntg * 8 + gid];
                    float b1 = kvs[(mc + 4) * KVPAD + ntg * 8 + gid];
                    mma8(oacc[nt], a0, a1, a2, a3, b0, b1);
                }
            }

            nrm0 += __shfl_xor_sync(0xffffffffu, nrm0, 1);
            nrm0 += __shfl_xor_sync(0xffffffffu, nrm0, 2);
            nrm1 += __shfl_xor_sync(0xffffffffu, nrm1, 1);
            nrm1 += __shfl_xor_sync(0xffffffffu, nrm1, 2);
            float inv0 = 1.0f / nrm0;
            float inv1 = 1.0f / nrm1;

            size_t orow = ((size_t)u * 64 + tr) * 64;
            #pragma unroll
            for (int nt = 0; nt < 4; nt++) {
                int col = (half * 4 + nt) * 8 + 2 * tq;
                float2 r0 = make_float2(oacc[nt].x * inv0, oacc[nt].y * inv0);
                float2 r1 = make_float2(oacc[nt].z * inv1, oacc[nt].w * inv1);
                *(float2*)(outp + orow + col)          = r0;
                *(float2*)(outp + orow + 8 * 64 + col) = r1;
            }
        }
    }
}

// ---------------------------------------------------------------------------
// launch
// ---------------------------------------------------------------------------
extern "C" void kernel_launch(void* const* d_in, const int* in_sizes, int n_in,
                              void* d_out, int out_size) {
    const float* query = (const float*)d_in[0];
    const float* value = (const float*)d_in[1];
    const float* key   = (const float*)d_in[2];
    const float* omega = (const float*)d_in[3];
    float* out = (float*)d_out;

    int nsm = 148;
    cudaDeviceGetAttribute(&nsm, cudaDevAttrMultiProcessorCount, 0);

    const int smem_b = B_TOT * (int)sizeof(float);   // union (B > A)
    cudaFuncSetAttribute(fused_kernel, cudaFuncAttributeMaxDynamicSharedMemorySize,
                         smem_b);

    fused_kernel<<<nsm, 256, smem_b>>>(query, value, key, omega, out);
}

// round 16
// speedup vs baseline: 1.1013x; 1.1013x over previous
#include <cuda_runtime.h>
#include <cuda_bf16.h>
#include <math.h>
#include <stdint.h>

#define Bb 8
#define Tt 8192
#define Ss 8192
#define Ff 64
#define Dd 64
#define EPSf 1e-9f
#define KVPAD 72
#define NCHUNK 1024   /* global 64-row chunks: 8 batches x 128 */

// kv scratch [b][256][72]; col 64 = normalizer, 65..71 stay zero
__device__ __align__(16) float g_kv[Bb * 256 * KVPAD];

// ---------------------------------------------------------------------------
// helpers
// ---------------------------------------------------------------------------
__device__ __forceinline__ float ftf32(float x) {
    unsigned u;
    asm("cvt.rna.tf32.f32 %0, %1;" : "=r"(u) : "f"(x));
    return __uint_as_float(u);
}

__device__ __forceinline__ uint32_t packbf(float x0, float x1) {
    uint32_t u;
    asm("cvt.rn.bf16x2.f32 %0, %1, %2;" : "=r"(u) : "f"(x1), "f"(x0));
    return u;
}

__device__ __forceinline__ void split2(float x0, float x1,
                                       uint32_t& hw, uint32_t& lw) {
    float h0 = __bfloat162float(__float2bfloat16(x0));
    float h1 = __bfloat162float(__float2bfloat16(x1));
    hw = packbf(x0, x1);
    lw = packbf(x0 - h0, x1 - h1);
}

// tf32 m16n8k8 (GEMM3/GEMM4)
__device__ __forceinline__ void mma8(float4& d,
                                     float a0, float a1, float a2, float a3,
                                     float b0, float b1) {
    asm("mma.sync.aligned.m16n8k8.row.col.f32.tf32.tf32.f32 "
        "{%0,%1,%2,%3},{%4,%5,%6,%7},{%8,%9},{%0,%1,%2,%3};"
        : "+f"(d.x), "+f"(d.y), "+f"(d.z), "+f"(d.w)
        : "r"(__float_as_uint(a0)), "r"(__float_as_uint(a1)),
          "r"(__float_as_uint(a2)), "r"(__float_as_uint(a3)),
          "r"(__float_as_uint(b0)), "r"(__float_as_uint(b1)));
}

// bf16 m16n8k16 (GEMM1)
__device__ __forceinline__ void mma16(float4& d,
                                      uint32_t a0, uint32_t a1,
                                      uint32_t a2, uint32_t a3,
                                      uint32_t b0, uint32_t b1) {
    asm("mma.sync.aligned.m16n8k16.row.col.f32.bf16.bf16.f32 "
        "{%0,%1,%2,%3},{%4,%5,%6,%7},{%8,%9},{%0,%1,%2,%3};"
        : "+f"(d.x), "+f"(d.y), "+f"(d.z), "+f"(d.w)
        : "r"(a0), "r"(a1), "r"(a2), "r"(a3), "r"(b0), "r"(b1));
}

// ---------------------------------------------------------------------------
// smem layouts (32-bit word offsets) — omega arrays eliminated (in registers)
// ---------------------------------------------------------------------------
// kernel A
#define A_KHI   0        /* [64][36]  packed bf16x2 hi */
#define A_KLO   2304     /* [64][36]  packed bf16x2 lo */
#define A_VS    4608     /* [64][72]  tf32 floats      */
#define A_PHT   9216     /* [256][68] tf32 floats      */
#define A_SSH   26624    /* [64] */
#define A_TOT   26688
// kernel B (64-row t-tiles, persistent)
#define B_QHI   0        /* [64][36]   */
#define B_QLO   2304     /* [64][36]   */
#define B_PHIQ  4608     /* [64][260]  */
#define B_KVS   21248    /* [256][72]  */
#define B_SSH   39680    /* [64]       */
#define B_TOT   39744

extern __shared__ float sm[];

// load this thread's loop-invariant omega B-fragments into registers:
// oh/ol[ks][nt][h] for m = w*16 + nt*8 + gid, word col = ks*8 + tq + h*4
__device__ __forceinline__ void load_omega_frags(const float* __restrict__ omega,
                                                 int w, int gid, int tq,
                                                 uint32_t oh[4][2][2],
                                                 uint32_t ol[4][2][2]) {
    #pragma unroll
    for (int ks = 0; ks < 4; ks++)
        #pragma unroll
        for (int nt = 0; nt < 2; nt++) {
            int m = w * 16 + nt * 8 + gid;
            #pragma unroll
            for (int h = 0; h < 2; h++) {
                int fw = ks * 8 + tq + h * 4;
                float2 o2 = *(const float2*)(omega + m * 64 + 2 * fw);
                split2(o2.x, o2.y, oh[ks][nt][h], ol[ks][nt][h]);
            }
        }
}

// ---------------------------------------------------------------------------
// Kernel A: persistent. Block walks contiguous 64-row chunks g in [lo, hi);
// global row = g*64 (batch = g>>7). Per chunk: GEMM1 split-bf16 (omega in
// regs), phi epilogue, GEMM3 tf32 accumulate; flush on batch change/end.
// ---------------------------------------------------------------------------
__global__ __launch_bounds__(256, 1)
void kv_kernel(const float* __restrict__ key,
               const float* __restrict__ value,
               const float* __restrict__ omega) {
    const int tid = threadIdx.x;
    const int w   = tid >> 5;
    const int ln  = tid & 31;
    const int gid = ln >> 2;
    const int tq  = ln & 3;
    const int r   = tid >> 2;
    const int qd  = tid & 3;

    const int lo = (int)(((long long)NCHUNK * blockIdx.x) / gridDim.x);
    const int hi = (int)(((long long)NCHUNK * (blockIdx.x + 1)) / gridDim.x);
    if (lo >= hi) return;

    uint32_t* Khi = (uint32_t*)(sm + A_KHI);
    uint32_t* Klo = (uint32_t*)(sm + A_KLO);
    float*    Vs  = sm + A_VS;
    float*    PhT = sm + A_PHT;
    float*    ssh = sm + A_SSH;

    uint32_t oh[4][2][2], ol[4][2][2];
    load_omega_frags(omega, w, gid, tq, oh, ol);

    float4 acc[2][8];
    #pragma unroll
    for (int mt = 0; mt < 2; mt++)
        #pragma unroll
        for (int nt = 0; nt < 8; nt++)
            acc[mt][nt] = make_float4(0.f, 0.f, 0.f, 0.f);
    float nrm[2][2] = {{0.f, 0.f}, {0.f, 0.f}};

    // preload chunk lo
    float4 kreg[4], vreg[4];
    {
        const float4* kg = (const float4*)(key   + ((size_t)lo * 64 + r) * Ff);
        const float4* vg = (const float4*)(value + ((size_t)lo * 64 + r) * Dd);
        #pragma unroll
        for (int j = 0; j < 4; j++) { kreg[j] = kg[qd * 4 + j]; vreg[j] = vg[qd * 4 + j]; }
    }

    for (int g = lo; g < hi; g++) {
        __syncthreads();   // previous-iter PhT/Vs/tile/ssh reads done

        // ---- store staged K (split bf16) / V (tf32); ssq via quad shfl ----
        {
            float ps = 0.f;
            #pragma unroll
            for (int j = 0; j < 4; j++) {
                int fj = qd * 4 + j;
                float4 x = kreg[j];
                ps += x.x * x.x + x.y * x.y + x.z * x.z + x.w * x.w;
                uint32_t hw, lw;
                split2(x.x, x.y, hw, lw);
                Khi[r * 36 + 2 * fj] = hw;  Klo[r * 36 + 2 * fj] = lw;
                split2(x.z, x.w, hw, lw);
                Khi[r * 36 + 2 * fj + 1] = hw;  Klo[r * 36 + 2 * fj + 1] = lw;
            }
            ps += __shfl_xor_sync(0xffffffffu, ps, 1);
            ps += __shfl_xor_sync(0xffffffffu, ps, 2);
            if (qd == 0) ssh[r] = 0.5f * ps;
            #pragma unroll
            for (int j = 0; j < 4; j++) {
                float4 x = vreg[j];
                float4 y;
                y.x = ftf32(x.x); y.y = ftf32(x.y); y.z = ftf32(x.z); y.w = ftf32(x.w);
                ((float4*)(Vs + r * 72))[qd * 4 + j] = y;
            }
            if (g + 1 < hi) {   // prefetch next chunk
                const float4* kg = (const float4*)(key   + ((size_t)(g + 1) * 64 + r) * Ff);
                const float4* vg = (const float4*)(value + ((size_t)(g + 1) * 64 + r) * Dd);
                #pragma unroll
                for (int j = 0; j < 4; j++) { kreg[j] = kg[qd * 4 + j]; vreg[j] = vg[qd * 4 + j]; }
            }
        }
        __syncthreads();

        // ---- XW = K . Omega^T (split-bf16 k16; omega frags in registers) ----
        float4 xw[4][2];
        #pragma unroll
        for (int mt = 0; mt < 4; mt++)
            #pragma unroll
            for (int nt = 0; nt < 2; nt++)
                xw[mt][nt] = make_float4(0.f, 0.f, 0.f, 0.f);

        #pragma unroll
        for (int ks = 0; ks < 4; ks++) {
            int f0w = ks * 8 + tq;
            #pragma unroll
            for (int mt = 0; mt < 4; mt++) {
                int s = mt * 16 + gid;
                uint32_t ah0 = Khi[s * 36 + f0w],       ah1 = Khi[(s + 8) * 36 + f0w];
                uint32_t ah2 = Khi[s * 36 + f0w + 4],   ah3 = Khi[(s + 8) * 36 + f0w + 4];
                uint32_t al0 = Klo[s * 36 + f0w],       al1 = Klo[(s + 8) * 36 + f0w];
                uint32_t al2 = Klo[s * 36 + f0w + 4],   al3 = Klo[(s + 8) * 36 + f0w + 4];
                #pragma unroll
                for (int nt = 0; nt < 2; nt++) {
                    mma16(xw[mt][nt], ah0, ah1, ah2, ah3, oh[ks][nt][0], oh[ks][nt][1]);
                    mma16(xw[mt][nt], al0, al1, al2, al3, oh[ks][nt][0], oh[ks][nt][1]);
                    mma16(xw[mt][nt], ah0, ah1, ah2, ah3, ol[ks][nt][0], ol[ks][nt][1]);
                }
            }
        }

        // ---- phi epilogue: PhT[m][s] = tf32(exp(+-xw - ss) + eps) ----
        #pragma unroll
        for (int mt = 0; mt < 4; mt++) {
            int s0 = mt * 16 + gid;
            float ssa = ssh[s0], ssb = ssh[s0 + 8];
            #pragma unroll
            for (int nt = 0; nt < 2; nt++) {
                int m0 = w * 16 + nt * 8 + 2 * tq;
                float4 v = xw[mt][nt];
                PhT[m0 * 68 + s0]             = ftf32(__expf( v.x - ssa) + EPSf);
                PhT[(m0 + 1) * 68 + s0]       = ftf32(__expf( v.y - ssa) + EPSf);
                PhT[m0 * 68 + s0 + 8]         = ftf32(__expf( v.z - ssb) + EPSf);
                PhT[(m0 + 1) * 68 + s0 + 8]   = ftf32(__expf( v.w - ssb) + EPSf);
                PhT[(m0 + 128) * 68 + s0]     = ftf32(__expf(-v.x - ssa) + EPSf);
                PhT[(m0 + 129) * 68 + s0]     = ftf32(__expf(-v.y - ssa) + EPSf);
                PhT[(m0 + 128) * 68 + s0 + 8] = ftf32(__expf(-v.z - ssb) + EPSf);
                PhT[(m0 + 129) * 68 + s0 + 8] = ftf32(__expf(-v.w - ssb) + EPSf);
            }
        }
        __syncthreads();

        // ---- acc += PhT . V (tf32 k8; warp w owns kv rows [32w,32w+32)) ----
        #pragma unroll 2
        for (int ks = 0; ks < 8; ks++) {
            float a[2][4];
            #pragma unroll
            for (int mt = 0; mt < 2; mt++) {
                int mr = 32 * w + mt * 16 + gid;
                int sc = ks * 8 + tq;
                a[mt][0] = PhT[mr * 68 + sc];
                a[mt][1] = PhT[(mr + 8) * 68 + sc];
                a[mt][2] = PhT[mr * 68 + sc + 4];
                a[mt][3] = PhT[(mr + 8) * 68 + sc + 4];
                nrm[mt][0] += a[mt][0] + a[mt][2];
                nrm[mt][1] += a[mt][1] + a[mt][3];
            }
            #pragma unroll
            for (int nt = 0; nt < 8; nt++) {
                float b0 = Vs[(ks * 8 + tq) * 72 + nt * 8 + gid];
                float b1 = Vs[(ks * 8 + tq + 4) * 72 + nt * 8 + gid];
                #pragma unroll
                for (int mt = 0; mt < 2; mt++)
                    mma8(acc[mt][nt], a[mt][0], a[mt][1], a[mt][2], a[mt][3], b0, b1);
            }
        }

        // ---- flush on batch change or range end ----
        if (g + 1 == hi || ((g + 1) >> 7) != (g >> 7)) {
            float* gp = g_kv + (size_t)(g >> 7) * 256 * KVPAD;
            #pragma unroll
            for (int mt = 0; mt < 2; mt++) {
                int m0 = 32 * w + mt * 16 + gid;
                #pragma unroll
                for (int nt = 0; nt < 8; nt++) {
                    int d0 = nt * 8 + 2 * tq;
                    atomicAdd(gp + m0 * KVPAD + d0,           acc[mt][nt].x);
                    atomicAdd(gp + m0 * KVPAD + d0 + 1,       acc[mt][nt].y);
                    atomicAdd(gp + (m0 + 8) * KVPAD + d0,     acc[mt][nt].z);
                    atomicAdd(gp + (m0 + 8) * KVPAD + d0 + 1, acc[mt][nt].w);
                    acc[mt][nt] = make_float4(0.f, 0.f, 0.f, 0.f);
                }
                float n0 = nrm[mt][0], n1 = nrm[mt][1];
                n0 += __shfl_xor_sync(0xffffffffu, n0, 1);
                n0 += __shfl_xor_sync(0xffffffffu, n0, 2);
                n1 += __shfl_xor_sync(0xffffffffu, n1, 1);
                n1 += __shfl_xor_sync(0xffffffffu, n1, 2);
                if (tq == 0) {
                    atomicAdd(gp + m0 * KVPAD + 64,       n0);
                    atomicAdd(gp + (m0 + 8) * KVPAD + 64, n1);
                }
                nrm[mt][0] = 0.f; nrm[mt][1] = 0.f;
            }
        }
    }
}

// ---------------------------------------------------------------------------
// Kernel B: persistent. Block walks contiguous 64-row t-tiles u in [lo, hi);
// omega frags in registers; kv reload on batch change.
// GEMM1 split-bf16 (M=64); GEMM4 tf32 warp-halves over 8 n-tiles.
// ---------------------------------------------------------------------------
__global__ __launch_bounds__(256, 1)
void out_kernel(const float* __restrict__ query,
                const float* __restrict__ omega,
                float* __restrict__ outp) {
    const int tid = threadIdx.x;
    const int w   = tid >> 5;
    const int ln  = tid & 31;
    const int gid = ln >> 2;
    const int tq  = ln & 3;
    const int r   = tid >> 2;
    const int qd  = tid & 3;

    const int lo = (int)(((long long)NCHUNK * blockIdx.x) / gridDim.x);
    const int hi = (int)(((long long)NCHUNK * (blockIdx.x + 1)) / gridDim.x);
    if (lo >= hi) return;

    uint32_t* Qhi  = (uint32_t*)(sm + B_QHI);
    uint32_t* Qlo  = (uint32_t*)(sm + B_QLO);
    float*    PhiQ = sm + B_PHIQ;
    float*    kvs  = sm + B_KVS;
    float*    ssh  = sm + B_SSH;

    uint32_t oh[4][2][2], ol[4][2][2];
    load_omega_frags(omega, w, gid, tq, oh, ol);

    int bcur = -1;

    for (int u = lo; u < hi; u++) {
        __syncthreads();   // prev tile's PhiQ/kvs/Q/ssh reads done
        const int b = u >> 7;

        if (b != bcur) {   // (re)load kv, tf32-rounded
            const float4* gk = (const float4*)(g_kv + (size_t)b * 256 * KVPAD);
            for (int i = tid; i < 256 * KVPAD / 4; i += 256) {
                float4 x = gk[i];
                float4 y;
                y.x = ftf32(x.x); y.y = ftf32(x.y); y.z = ftf32(x.z); y.w = ftf32(x.w);
                ((float4*)kvs)[i] = y;
            }
            bcur = b;
        }

        // Q tile (64 rows): split bf16 + ssq via quad shfl
        {
            const float4* qg = (const float4*)(query + ((size_t)u * 64 + r) * Ff);
            float ps = 0.f;
            #pragma unroll
            for (int j = 0; j < 4; j++) {
                int fj = qd * 4 + j;
                float4 x = qg[fj];
                ps += x.x * x.x + x.y * x.y + x.z * x.z + x.w * x.w;
                uint32_t hw, lw;
                split2(x.x, x.y, hw, lw);
                Qhi[r * 36 + 2 * fj] = hw;  Qlo[r * 36 + 2 * fj] = lw;
                split2(x.z, x.w, hw, lw);
                Qhi[r * 36 + 2 * fj + 1] = hw;  Qlo[r * 36 + 2 * fj + 1] = lw;
            }
            ps += __shfl_xor_sync(0xffffffffu, ps, 1);
            ps += __shfl_xor_sync(0xffffffffu, ps, 2);
            if (qd == 0) ssh[r] = 0.5f * ps;
        }
        __syncthreads();

        // ---- XW = Q . Omega^T (split-bf16 k16; omega frags in registers) ----
        float4 xw[4][2];
        #pragma unroll
        for (int mt = 0; mt < 4; mt++)
            #pragma unroll
            for (int nt = 0; nt < 2; nt++)
                xw[mt][nt] = make_float4(0.f, 0.f, 0.f, 0.f);

        #pragma unroll
        for (int ks = 0; ks < 4; ks++) {
            int f0w = ks * 8 + tq;
            #pragma unroll
            for (int mt = 0; mt < 4; mt++) {
                int t = mt * 16 + gid;
                uint32_t ah0 = Qhi[t * 36 + f0w],       ah1 = Qhi[(t + 8) * 36 + f0w];
                uint32_t ah2 = Qhi[t * 36 + f0w + 4],   ah3 = Qhi[(t + 8) * 36 + f0w + 4];
                uint32_t al0 = Qlo[t * 36 + f0w],       al1 = Qlo[(t + 8) * 36 + f0w];
                uint32_t al2 = Qlo[t * 36 + f0w + 4],   al3 = Qlo[(t + 8) * 36 + f0w + 4];
                #pragma unroll
                for (int nt = 0; nt < 2; nt++) {
                    mma16(xw[mt][nt], ah0, ah1, ah2, ah3, oh[ks][nt][0], oh[ks][nt][1]);
                    mma16(xw[mt][nt], al0, al1, al2, al3, oh[ks][nt][0], oh[ks][nt][1]);
                    mma16(xw[mt][nt], ah0, ah1, ah2, ah3, ol[ks][nt][0], ol[ks][nt][1]);
                }
            }
        }

        // ---- phi epilogue: PhiQ[t][m] = tf32(exp(+-xw - ss) + eps) ----
        #pragma unroll
        for (int mt = 0; mt < 4; mt++) {
            int t = mt * 16 + gid;
            float ssa = ssh[t], ssb = ssh[t + 8];
            #pragma unroll
            for (int nt = 0; nt < 2; nt++) {
                int m0 = w * 16 + nt * 8 + 2 * tq;
                float4 v = xw[mt][nt];
                PhiQ[t * 260 + m0]             = ftf32(__expf( v.x - ssa) + EPSf);
                PhiQ[t * 260 + m0 + 1]         = ftf32(__expf( v.y - ssa) + EPSf);
                PhiQ[(t + 8) * 260 + m0]       = ftf32(__expf( v.z - ssb) + EPSf);
                PhiQ[(t + 8) * 260 + m0 + 1]   = ftf32(__expf( v.w - ssb) + EPSf);
                PhiQ[t * 260 + m0 + 128]       = ftf32(__expf(-v.x - ssa) + EPSf);
                PhiQ[t * 260 + m0 + 129]       = ftf32(__expf(-v.y - ssa) + EPSf);
                PhiQ[(t + 8) * 260 + m0 + 128] = ftf32(__expf(-v.z - ssb) + EPSf);
                PhiQ[(t + 8) * 260 + m0 + 129] = ftf32(__expf(-v.w - ssb) + EPSf);
            }
        }
        __syncthreads();

        // ---- out = PhiQ . kv (tf32 k8; warp-halves: wr owns 16 t-rows,
        //      half 0 -> n-tiles 0..3, half 1 -> n-tiles 4..7) ----
        const int half = w >> 2;
        const int wr   = w & 3;
        const int tr   = 16 * wr + gid;

        float4 oacc[4];
        #pragma unroll
        for (int nt = 0; nt < 4; nt++) oacc[nt] = make_float4(0.f, 0.f, 0.f, 0.f);
        float nrm0 = 0.f, nrm1 = 0.f;

        #pragma unroll 4
        for (int ks = 0; ks < 32; ks++) {
            int mc = ks * 8 + tq;
            float a0 = PhiQ[tr * 260 + mc],       a1 = PhiQ[(tr + 8) * 260 + mc];
            float a2 = PhiQ[tr * 260 + mc + 4],   a3 = PhiQ[(tr + 8) * 260 + mc + 4];
            float kn0 = kvs[mc * KVPAD + 64];
            float kn1 = kvs[(mc + 4) * KVPAD + 64];
            nrm0 += a0 * kn0 + a2 * kn1;
            nrm1 += a1 * kn0 + a3 * kn1;
            #pragma unroll
            for (int nt = 0; nt < 4; nt++) {
                int ntg = half * 4 + nt;
                float b0 = kvs[mc * KVPAD + ntg * 8 + gid];
                float b1 = kvs[(mc + 4) * KVPAD + ntg * 8 + gid];
                mma8(oacc[nt], a0, a1, a2, a3, b0, b1);
            }
        }

        nrm0 += __shfl_xor_sync(0xffffffffu, nrm0, 1);
        nrm0 += __shfl_xor_sync(0xffffffffu, nrm0, 2);
        nrm1 += __shfl_xor_sync(0xffffffffu, nrm1, 1);
        nrm1 += __shfl_xor_sync(0xffffffffu, nrm1, 2);
        float inv0 = 1.0f / nrm0;
        float inv1 = 1.0f / nrm1;

        size_t orow = ((size_t)u * 64 + tr) * 64;
        #pragma unroll
        for (int nt = 0; nt < 4; nt++) {
            int col = (half * 4 + nt) * 8 + 2 * tq;
            float2 r0 = make_float2(oacc[nt].x * inv0, oacc[nt].y * inv0);
            float2 r1 = make_float2(oacc[nt].z * inv1, oacc[nt].w * inv1);
            *(float2*)(outp + orow + col)          = r0;
            *(float2*)(outp + orow + 8 * 64 + col) = r1;
        }
    }
}

// ---------------------------------------------------------------------------
// launch
// ---------------------------------------------------------------------------
extern "C" void kernel_launch(void* const* d_in, const int* in_sizes, int n_in,
                              void* d_out, int out_size) {
    const float* query = (const float*)d_in[0];
    const float* value = (const float*)d_in[1];
    const float* key   = (const float*)d_in[2];
    const float* omega = (const float*)d_in[3];
    float* out = (float*)d_out;

    int nsm = 148;
    cudaDeviceGetAttribute(&nsm, cudaDevAttrMultiProcessorCount, 0);

    cudaFuncSetAttribute(kv_kernel,  cudaFuncAttributeMaxDynamicSharedMemorySize,
                         A_TOT * (int)sizeof(float));
    cudaFuncSetAttribute(out_kernel, cudaFuncAttributeMaxDynamicSharedMemorySize,
                         B_TOT * (int)sizeof(float));

    void* kvptr = nullptr;
    cudaGetSymbolAddress(&kvptr, g_kv);
    cudaMemsetAsync(kvptr, 0, Bb * 256 * KVPAD * sizeof(float));

    kv_kernel<<<nsm, 256, A_TOT * sizeof(float)>>>(key, value, omega);
    out_kernel<<<nsm, 256, B_TOT * sizeof(float)>>>(query, omega, out);
}